// round 4
// baseline (speedup 1.0000x reference)
#include <cuda_runtime.h>
#include <math.h>

#define BB 4
#define CC 128
#define NBOX 4
#define BTC 32
#define HH 256
#define WW 256
#define HWSZ (HH*WW)
#define SWP 260                     // padded integral row stride (16B-aligned rows)

// scratch (static device globals; no dynamic allocation)
__device__ float g_z[BB*BTC*HH*WW];       // z = BN1(conv); column-cumsum'd IN PLACE
__device__ float g_S[BB*BTC*SWP*257];     // 2D integral image, rows padded to 260

// ---------------------------------------------------------------------------
// Kernel 1: z = BN1(x @ w1^T)  — register-tiled GEMM
// ---------------------------------------------------------------------------
__global__ __launch_bounds__(256) void k1_conv_bn(
    const float* __restrict__ x, const float* __restrict__ w1,
    const float* __restrict__ g1, const float* __restrict__ b1,
    const float* __restrict__ m1, const float* __restrict__ v1)
{
    __shared__ float xs[32][256];
    __shared__ float ws[128][32];

    const int tid = threadIdx.x;

    for (int idx = tid; idx < CC*BTC; idx += 256) {
        int k = idx & 31;
        int c = idx >> 5;
        float inv = g1[k] * rsqrtf(v1[k] + 1e-5f);
        ws[c][k] = w1[k*CC + c] * inv;
    }

    const int pixbase = blockIdx.x * 256;
    const int b  = pixbase >> 16;
    const int ij = pixbase & 65535;
    const float* xp = x + (size_t)b*CC*HWSZ + ij;

    const int tp = tid & 63;
    const int tk = tid >> 6;

    float acc[4][8];
    #pragma unroll
    for (int p = 0; p < 4; p++)
        #pragma unroll
        for (int q = 0; q < 8; q++) acc[p][q] = 0.f;

    const int cl = tid >> 6;
    const int p4 = (tid & 63) * 4;

    for (int kc = 0; kc < CC; kc += 32) {
        __syncthreads();
        #pragma unroll
        for (int it = 0; it < 8; it++) {
            int c = kc + it*4 + cl;
            float4 v = *(const float4*)(xp + (size_t)c*HWSZ + p4);
            *(float4*)&xs[it*4 + cl][p4] = v;
        }
        __syncthreads();

        #pragma unroll
        for (int c = 0; c < 32; c++) {
            float4 xv = *(float4*)&xs[c][tp*4];
            float4 wa = *(float4*)&ws[kc + c][tk*8];
            float4 wb = *(float4*)&ws[kc + c][tk*8 + 4];
            float xr[4] = {xv.x, xv.y, xv.z, xv.w};
            float wr[8] = {wa.x, wa.y, wa.z, wa.w, wb.x, wb.y, wb.z, wb.w};
            #pragma unroll
            for (int p = 0; p < 4; p++)
                #pragma unroll
                for (int q = 0; q < 8; q++)
                    acc[p][q] += xr[p] * wr[q];
        }
    }

    #pragma unroll
    for (int q = 0; q < 8; q++) {
        int k = tk*8 + q;
        float inv  = g1[k] * rsqrtf(v1[k] + 1e-5f);
        float bias = b1[k] - m1[k]*inv;
        float4 r = make_float4(acc[0][q] + bias, acc[1][q] + bias,
                               acc[2][q] + bias, acc[3][q] + bias);
        *(float4*)(g_z + (size_t)(b*BTC + k)*HWSZ + ij + tp*4) = r;
    }
}

// ---------------------------------------------------------------------------
// Kernel 2a: column cumsum IN PLACE on g_z, chunked over rows (4 chunks of 64)
// ---------------------------------------------------------------------------
__global__ __launch_bounds__(256) void k2a_colsum()
{
    const int plane = blockIdx.y;
    const int chunk = blockIdx.x;
    const int j     = threadIdx.x;
    float* zp = g_z + (size_t)plane*HWSZ + (size_t)(chunk*64)*WW + j;
    float acc = 0.f;
    #pragma unroll 8
    for (int r = 0; r < 64; r++) {
        acc += zp[(size_t)r*WW];
        zp[(size_t)r*WW] = acc;
    }
}

// ---------------------------------------------------------------------------
// Kernel 2b: build S row i (0..256): stitch chunk offsets, row prefix-scan.
// ---------------------------------------------------------------------------
__global__ __launch_bounds__(256) void k2b_rowscan()
{
    __shared__ float wsum[8];
    const int plane = blockIdx.x / 257;
    const int i     = blockIdx.x % 257;     // 0..256
    const int j     = threadIdx.x;

    float v = 0.f;
    if (i > 0) {
        const float* zp = g_z + (size_t)plane*HWSZ + j;
        int r = i - 1;
        int q = r >> 6;
        v = zp[(size_t)r*WW];
        for (int p = 0; p < q; p++)
            v += zp[(size_t)(p*64 + 63)*WW];
    }

    const int lane = j & 31, warp = j >> 5;
    float s = v;
    #pragma unroll
    for (int o = 1; o < 32; o <<= 1) {
        float t = __shfl_up_sync(0xffffffffu, s, o);
        if (lane >= o) s += t;
    }
    if (lane == 31) wsum[warp] = s;
    __syncthreads();
    if (warp == 0) {
        float t = (lane < 8) ? wsum[lane] : 0.f;
        #pragma unroll
        for (int o = 1; o < 8; o <<= 1) {
            float u = __shfl_up_sync(0xffffffffu, t, o);
            if (lane >= o) t += u;
        }
        if (lane < 8) wsum[lane] = t;
    }
    __syncthreads();
    float incl = s + ((warp > 0) ? wsum[warp-1] : 0.f);

    float* Sr = g_S + (size_t)plane*SWP*257 + (size_t)i*SWP;
    if (j == 0) Sr[0] = 0.f;
    Sr[j+1] = incl;
}

// ---------------------------------------------------------------------------
// Kernel 3: separable box filter, vectorized.
// block = (b,bt,nb, 8-row chunk); thread = 4 consecutive cols.
// Phase 1: Dv via LDG.128 S taps, stored interleaved by col%4 (conflict-free).
// Phase 2: 4 scalar LDS/px + float4 x/out.
// ---------------------------------------------------------------------------
__global__ __launch_bounds__(256) void k3_box(
    const float* __restrict__ x,
    const float* __restrict__ xmn_, const float* __restrict__ xmx_,
    const float* __restrict__ ymn_, const float* __restrict__ ymx_,
    const float* __restrict__ g2, const float* __restrict__ b2,
    const float* __restrict__ m2, const float* __restrict__ v2,
    float* __restrict__ out)
{
    __shared__ float DvM[4][8][66];   // [c&3][row][c>>2], c = 0..256

    const int bid = blockIdx.x;
    const int rc  = bid & 31;
    const int nb  = (bid >> 5) & (NBOX-1);
    const int bt  = (bid >> 7) & (BTC-1);
    const int b   = bid >> 12;
    const int tid = threadIdx.x;
    const int rg  = tid >> 6;          // 0..3 : handles rows rg*2, rg*2+1 in phase 1
    const int ct  = tid & 63;          // col group
    const int c4  = ct * 4;
    const int k   = bt*NBOX + nb;
    const int boxi = bt*NBOX + nb;

    const float xmn = xmn_[boxi], xmx = xmx_[boxi];
    const float ymn = ymn_[boxi], ymx = ymx_[boxi];
    const float inv_area = 1.f / ((xmx - xmn) * (ymx - ymn));

    const float* Sp = g_S + (size_t)(b*BTC + bt)*SWP*257;

    // ---- phase 1: vertical lerp-difference, 2 rows per thread, float4 cols ----
    #pragma unroll
    for (int rr = 0; rr < 2; rr++) {
        int r = rg*2 + rr;
        int i = rc*8 + r;
        float uA = fminf(fmaxf((float)i + xmx, 0.f), 256.f);
        float uB = fminf(fmaxf((float)i + xmn, 0.f), 256.f);
        float fA = fminf(floorf(uA), 255.f);
        float fB = fminf(floorf(uB), 255.f);
        int   iA = (int)fA, iB = (int)fB;
        float wA = uA - fA, wB = uB - fB;

        const float* RA = Sp + (size_t)iA*SWP;
        const float* RB = Sp + (size_t)iB*SWP;

        float4 a0 = *(const float4*)(RA + c4);
        float4 a1 = *(const float4*)(RA + SWP + c4);
        float4 b0 = *(const float4*)(RB + c4);
        float4 b1 = *(const float4*)(RB + SWP + c4);

        DvM[0][r][ct] = (a0.x*(1.f-wA) + a1.x*wA) - (b0.x*(1.f-wB) + b1.x*wB);
        DvM[1][r][ct] = (a0.y*(1.f-wA) + a1.y*wA) - (b0.y*(1.f-wB) + b1.y*wB);
        DvM[2][r][ct] = (a0.z*(1.f-wA) + a1.z*wA) - (b0.z*(1.f-wB) + b1.z*wB);
        DvM[3][r][ct] = (a0.w*(1.f-wA) + a1.w*wA) - (b0.w*(1.f-wB) + b1.w*wB);

        if (ct == 63) {   // col 256
            float s0 = RA[256], s1 = RA[SWP+256];
            float t0 = RB[256], t1 = RB[SWP+256];
            DvM[0][r][64] = (s0*(1.f-wA) + s1*wA) - (t0*(1.f-wB) + t1*wB);
        }
    }
    __syncthreads();

    // ---- phase 2: horizontal fractional box from interleaved smem ----
    int   jA[4], jB[4];
    float wvA[4], wvB[4];
    #pragma unroll
    for (int t = 0; t < 4; t++) {
        int j = c4 + t;
        float vA = fminf(fmaxf((float)j + ymx, 0.f), 256.f);
        float vB = fminf(fmaxf((float)j + ymn, 0.f), 256.f);
        float gA = fminf(floorf(vA), 255.f);
        float gB = fminf(floorf(vB), 255.f);
        jA[t] = (int)gA;  jB[t] = (int)gB;
        wvA[t] = vA - gA; wvB[t] = vB - gB;
    }

    float inv2  = g2[k] * rsqrtf(v2[k] + 1e-3f);
    float bias2 = b2[k] - m2[k]*inv2;

    const float* xrow = x   + ((size_t)(b*CC + k)*HH + rc*8)*WW + c4;
    float*       orow = out + ((size_t)(b*CC + k)*HH + rc*8)*WW + c4;

    #pragma unroll
    for (int r = 0; r < 8; r++) {
        float4 xv = *(const float4*)(xrow + (size_t)r*WW);
        float xa[4] = {xv.x, xv.y, xv.z, xv.w};
        float oa[4];
        #pragma unroll
        for (int t = 0; t < 4; t++) {
            int a0 = jA[t], a1 = jA[t] + 1;
            int b0 = jB[t], b1 = jB[t] + 1;
            float DA = DvM[a0 & 3][r][a0 >> 2]*(1.f - wvA[t])
                     + DvM[a1 & 3][r][a1 >> 2]*wvA[t];
            float DB = DvM[b0 & 3][r][b0 >> 2]*(1.f - wvB[t])
                     + DvM[b1 & 3][r][b1 >> 2]*wvB[t];
            float val = (DA - DB) * inv_area;
            val = fmaxf(val*inv2 + bias2, 0.f);
            oa[t] = fmaxf(xa[t] + val, 0.f);
        }
        *(float4*)(orow + (size_t)r*WW) = make_float4(oa[0], oa[1], oa[2], oa[3]);
    }
}

// ---------------------------------------------------------------------------
extern "C" void kernel_launch(void* const* d_in, const int* in_sizes, int n_in,
                              void* d_out, int out_size)
{
    const float* x    = (const float*)d_in[0];
    const float* w1   = (const float*)d_in[1];
    const float* g1   = (const float*)d_in[2];
    const float* b1   = (const float*)d_in[3];
    const float* m1   = (const float*)d_in[4];
    const float* v1   = (const float*)d_in[5];
    const float* xmn  = (const float*)d_in[6];
    const float* xmx  = (const float*)d_in[7];
    const float* ymn  = (const float*)d_in[8];
    const float* ymx  = (const float*)d_in[9];
    const float* g2   = (const float*)d_in[10];
    const float* b2   = (const float*)d_in[11];
    const float* m2   = (const float*)d_in[12];
    const float* v2   = (const float*)d_in[13];
    float* out = (float*)d_out;

    k1_conv_bn<<<(BB*HWSZ)/256, 256>>>(x, w1, g1, b1, m1, v1);
    k2a_colsum<<<dim3(4, BB*BTC), 256>>>();
    k2b_rowscan<<<BB*BTC*257, 256>>>();
    k3_box<<<BB*BTC*NBOX*(HH/8), 256>>>(x, xmn, xmx, ymn, ymx, g2, b2, m2, v2, out);
}